// round 2
// baseline (speedup 1.0000x reference)
#include <cuda_runtime.h>

// Problem constants (from reference)
#define CUBE_L   512
#define EQU_H    1024
#define EQU_W    2048
#define N_EQU    4
#define N_CH     3
#define N_PIX    (EQU_H * EQU_W)        // 2,097,152
#define LL       (CUBE_L * CUBE_L)      // 262,144

__global__ __launch_bounds__(256)
void cube2equirec_kernel(const float* __restrict__ x,
                         const float2* __restrict__ uv,
                         const int* __restrict__ face,
                         float* __restrict__ out)
{
    int p = blockIdx.x * blockDim.x + threadIdx.x;
    if (p >= N_PIX) return;

    float2 t = uv[p];
    float u = t.x, v = t.y;
    int f = face[p];

    // Match reference: x0 = clip(floor(u), 0, L-1); x1 = min(x0+1, L-1); wx = u - x0
    int x0 = (int)floorf(u);
    int y0 = (int)floorf(v);
    x0 = min(max(x0, 0), CUBE_L - 1);
    y0 = min(max(y0, 0), CUBE_L - 1);
    int x1 = min(x0 + 1, CUBE_L - 1);
    int y1 = min(y0 + 1, CUBE_L - 1);
    float wx = u - (float)x0;
    float wy = v - (float)y0;

    float w00 = (1.0f - wx) * (1.0f - wy);
    float w01 = wx * (1.0f - wy);
    float w10 = (1.0f - wx) * wy;
    float w11 = wx * wy;

    int o00 = y0 * CUBE_L + x0;
    int o01 = y0 * CUBE_L + x1;
    int o10 = y1 * CUBE_L + x0;
    int o11 = y1 * CUBE_L + x1;

    int base_f = f * (N_CH * LL);   // face offset within a group of 6 faces

    #pragma unroll
    for (int e = 0; e < N_EQU; e++) {
        const float* xe = x + e * (6 * N_CH * LL) + base_f;
        #pragma unroll
        for (int c = 0; c < N_CH; c++) {
            const float* xc = xe + c * LL;
            float g00 = __ldg(xc + o00);
            float g01 = __ldg(xc + o01);
            float g10 = __ldg(xc + o10);
            float g11 = __ldg(xc + o11);
            float r = g00 * w00 + g01 * w01 + g10 * w10 + g11 * w11;
            out[(e * N_CH + c) * N_PIX + p] = r;
        }
    }
}

extern "C" void kernel_launch(void* const* d_in, const int* in_sizes, int n_in,
                              void* d_out, int out_size)
{
    const float*  x    = (const float*)d_in[0];
    const float2* uv   = (const float2*)d_in[1];
    const int*    face = (const int*)d_in[2];
    float*        out  = (float*)d_out;

    int threads = 256;
    int blocks = (N_PIX + threads - 1) / threads;
    cube2equirec_kernel<<<blocks, threads>>>(x, uv, face, out);
}

// round 3
// speedup vs baseline: 1.5311x; 1.5311x over previous
#include <cuda_runtime.h>

// Problem constants (from reference)
#define CUBE_L   512
#define EQU_H    1024
#define EQU_W    2048
#define N_EQU    4
#define N_CH     3
#define N_PIX    (EQU_H * EQU_W)        // 2,097,152
#define LL       (CUBE_L * CUBE_L)      // 262,144

// 32x8 pixel tile per block: warp = one row of 32 pixels (coalesced stores),
// 8 rows per block for 2D gather locality on the cube faces.
__global__ __launch_bounds__(256)
void cube2equirec_kernel(const float* __restrict__ x,
                         const float2* __restrict__ uv,
                         const int* __restrict__ face,
                         float* __restrict__ out)
{
    const int px = blockIdx.x * 32 + threadIdx.x;   // 0..2047
    const int py = blockIdx.y * 8  + threadIdx.y;   // 0..1023
    const int p  = py * EQU_W + px;

    const float2 t = uv[p];
    const float u = t.x, v = t.y;
    const int f = face[p];

    int x0 = (int)floorf(u);
    int y0 = (int)floorf(v);
    x0 = min(max(x0, 0), CUBE_L - 1);
    y0 = min(max(y0, 0), CUBE_L - 1);
    const int x1 = min(x0 + 1, CUBE_L - 1);
    const int y1 = min(y0 + 1, CUBE_L - 1);
    const float wx = u - (float)x0;
    const float wy = v - (float)y0;

    const float w00 = (1.0f - wx) * (1.0f - wy);
    const float w01 = wx * (1.0f - wy);
    const float w10 = (1.0f - wx) * wy;
    const float w11 = wx * wy;

    const int o00 = y0 * CUBE_L + x0;
    const int o01 = y0 * CUBE_L + x1;
    const int o10 = y1 * CUBE_L + x0;
    const int o11 = y1 * CUBE_L + x1;

    const float* xf = x + (size_t)f * (N_CH * LL);

    #pragma unroll
    for (int e = 0; e < N_EQU; e++) {
        const float* xe = xf + (size_t)e * (6 * N_CH * LL);

        // Issue all 12 gathers for this equirect image before any math:
        // 12 outstanding loads per warp for latency hiding.
        float g[N_CH][4];
        #pragma unroll
        for (int c = 0; c < N_CH; c++) {
            const float* xc = xe + c * LL;
            g[c][0] = __ldg(xc + o00);
            g[c][1] = __ldg(xc + o01);
            g[c][2] = __ldg(xc + o10);
            g[c][3] = __ldg(xc + o11);
        }

        #pragma unroll
        for (int c = 0; c < N_CH; c++) {
            float r = g[c][0] * w00 + g[c][1] * w01
                    + g[c][2] * w10 + g[c][3] * w11;
            out[(size_t)(e * N_CH + c) * N_PIX + p] = r;
        }
    }
}

extern "C" void kernel_launch(void* const* d_in, const int* in_sizes, int n_in,
                              void* d_out, int out_size)
{
    const float*  x    = (const float*)d_in[0];
    const float2* uv   = (const float2*)d_in[1];
    const int*    face = (const int*)d_in[2];
    float*        out  = (float*)d_out;

    dim3 block(32, 8);
    dim3 grid(EQU_W / 32, EQU_H / 8);
    cube2equirec_kernel<<<grid, block>>>(x, uv, face, out);
}

// round 4
// speedup vs baseline: 1.5921x; 1.0398x over previous
#include <cuda_runtime.h>

// Problem constants (from reference)
#define CUBE_L   512
#define EQU_H    1024
#define EQU_W    2048
#define N_EQU    4
#define N_CH     3
#define N_PIX    (EQU_H * EQU_W)        // 2,097,152
#define LL       (CUBE_L * CUBE_L)      // 262,144
#define NPLANE   (N_EQU * N_CH)         // 12

// 32x8 pixel tile per block; each thread handles one equirect pixel for all
// 12 output planes. All 48 gather loads are issued before any FMA to maximize
// per-warp MLP (L1 latency hiding). __launch_bounds__(256,3) lets ptxas use
// ~85 regs so the batch actually stays register-resident.
__global__ __launch_bounds__(256, 3)
void cube2equirec_kernel(const float* __restrict__ x,
                         const float2* __restrict__ uv,
                         const int* __restrict__ face,
                         float* __restrict__ out)
{
    const int px = blockIdx.x * 32 + threadIdx.x;   // 0..2047
    const int py = blockIdx.y * 8  + threadIdx.y;   // 0..1023
    const int p  = py * EQU_W + px;

    const float2 t = uv[p];
    const float u = t.x, v = t.y;
    const int f = face[p];

    int x0 = (int)floorf(u);
    int y0 = (int)floorf(v);
    x0 = min(max(x0, 0), CUBE_L - 1);
    y0 = min(max(y0, 0), CUBE_L - 1);
    const int x1 = min(x0 + 1, CUBE_L - 1);
    const int y1 = min(y0 + 1, CUBE_L - 1);
    const float wx = u - (float)x0;
    const float wy = v - (float)y0;

    const float w00 = (1.0f - wx) * (1.0f - wy);
    const float w01 = wx * (1.0f - wy);
    const float w10 = (1.0f - wx) * wy;
    const float w11 = wx * wy;

    const int o00 = y0 * CUBE_L + x0;
    const int o01 = y0 * CUBE_L + x1;
    const int o10 = y1 * CUBE_L + x0;
    const int o11 = y1 * CUBE_L + x1;

    // Base of face f, channel 0, image 0. Plane i = (e*3 + c) advances by LL
    // within an image and by 18*LL between images; flattening: plane stride
    // pattern is e*(18*LL) + c*LL.
    const float* xf = x + f * (N_CH * LL);

    // ---- Phase 1: issue all 48 gathers ----
    float g00[NPLANE], g01[NPLANE], g10[NPLANE], g11[NPLANE];
    #pragma unroll
    for (int e = 0; e < N_EQU; e++) {
        #pragma unroll
        for (int c = 0; c < N_CH; c++) {
            const float* xc = xf + e * (6 * N_CH * LL) + c * LL;
            const int i = e * N_CH + c;
            g00[i] = __ldg(xc + o00);
            g01[i] = __ldg(xc + o01);
            g10[i] = __ldg(xc + o10);
            g11[i] = __ldg(xc + o11);
        }
    }

    // ---- Phase 2: blend + streaming stores ----
    #pragma unroll
    for (int i = 0; i < NPLANE; i++) {
        float r = g00[i] * w00 + g01[i] * w01 + g10[i] * w10 + g11[i] * w11;
        __stcs(out + (size_t)i * N_PIX + p, r);
    }
}

extern "C" void kernel_launch(void* const* d_in, const int* in_sizes, int n_in,
                              void* d_out, int out_size)
{
    const float*  x    = (const float*)d_in[0];
    const float2* uv   = (const float2*)d_in[1];
    const int*    face = (const int*)d_in[2];
    float*        out  = (float*)d_out;

    dim3 block(32, 8);
    dim3 grid(EQU_W / 32, EQU_H / 8);
    cube2equirec_kernel<<<grid, block>>>(x, uv, face, out);
}